// round 12
// baseline (speedup 1.0000x reference)
#include <cuda_runtime.h>
#include <cstddef>

// Math collapse (B=1, L=2048, DIM=16, HEADS=DIM_HEAD=1):
// softmax over size-1 axis == 1  =>  out[i, j, d] = v[i]*W_out[d] + b_out[d],
// v[i] = dot(x[i,:], W_qkv[2,:]).  Output (1,2048,2048,16) fp32 = 268 MB.
//
// Store-roofline kernel, round 8: identical dataflow to the best variants
// (one row per CTA, register-held pattern, evict-first streaming stores),
// but using sm_100a+ 256-bit stores (st.global.cs.v8.f32 -> STG.E.256):
// half the store instructions and half the L1 store wavefronts per byte.

#define L_TOKENS  2048
#define DIM_IN    16
#define ROW_F8    4096                   // 32B-chunks per i-row (2048*16/8)
#define ROW_FLTS  (L_TOKENS * DIM_IN)    // 32768 floats per i-row
#define THREADS   256

__global__ __launch_bounds__(THREADS, 8)
void attn_broadcast_v8_kernel(const float* __restrict__ x,
                              const float* __restrict__ Wqkv,   // (3,16); v-row at +32
                              const float* __restrict__ Wout,   // (16,1)
                              const float* __restrict__ bout,   // (16,)
                              float* __restrict__ out)
{
    const int i   = blockIdx.x;
    const int tid = threadIdx.x;

    // v[i] = dot(x[i, 0:16], Wqkv[2, 0:16]) — all loads are L1-broadcast
    // (same address warp-wide), computed redundantly per thread: no smem,
    // no __syncthreads.
    const float4* xr = (const float4*)(x + i * DIM_IN);
    const float4* wv = (const float4*)(Wqkv + 2 * DIM_IN);
    float v = 0.0f;
    #pragma unroll
    for (int q = 0; q < 4; ++q) {
        float4 a = xr[q], b = wv[q];
        v = fmaf(a.x, b.x, v); v = fmaf(a.y, b.y, v);
        v = fmaf(a.z, b.z, v); v = fmaf(a.w, b.w, v);
    }

    // Each 32B slot s covers dims (s & 1)*8 .. +8. THREADS and ROW_F8 are
    // even, so (k & 1) == (tid & 1) for every store this thread makes.
    const int d_base = (tid & 1) * 8;
    float p[8];
    #pragma unroll
    for (int d = 0; d < 8; ++d)
        p[d] = fmaf(v, Wout[d_base + d], bout[d_base + d]);

    float* row = out + (size_t)i * ROW_FLTS;

    // 256-bit evict-first streaming stores (STG.E.256): 16 iterations/thread,
    // perfectly coalesced — each warp covers 1024B (8 sectors) per issue.
    #pragma unroll 8
    for (int k = tid; k < ROW_F8; k += THREADS) {
        float* dst = row + (size_t)k * 8;
        asm volatile(
            "st.global.cs.v8.f32 [%0], {%1, %2, %3, %4, %5, %6, %7, %8};"
            :: "l"(dst),
               "f"(p[0]), "f"(p[1]), "f"(p[2]), "f"(p[3]),
               "f"(p[4]), "f"(p[5]), "f"(p[6]), "f"(p[7])
            : "memory");
    }
}

extern "C" void kernel_launch(void* const* d_in, const int* in_sizes, int n_in,
                              void* d_out, int out_size)
{
    const float* x    = (const float*)d_in[0];   // (1, 2048, 16)
    const float* Wqkv = (const float*)d_in[1];   // (3, 16)
    const float* Wout = (const float*)d_in[2];   // (16, 1)
    const float* bout = (const float*)d_in[3];   // (16,)
    float* out = (float*)d_out;                  // (1, 2048, 2048, 16) fp32

    attn_broadcast_v8_kernel<<<L_TOKENS, THREADS>>>(x, Wqkv, Wout, bout, out);
}